// round 5
// baseline (speedup 1.0000x reference)
#include <cuda_runtime.h>
#include <cstdint>

// ---------------------------------------------------------------------------
// ChaoticLSTM: bs=64, seq=512, in=128, H=256, 4H=1024, T=512
//   Phase 1: xproj[32768][1024] = X[32768][128] @ Wi[128][1024] + B
//   Phase 2: register-stationary-Wh recurrence, 16 clusters x 8 CTAs x 512 thr.
//     R5: per-step sync is a DSMEM mbarrier protocol (128 arrivals = 16 warps
//     x 8 CTAs) instead of barrier.cluster. No thread rendezvous in the loop;
//     warps run independently, gated only by data arrival.
// ---------------------------------------------------------------------------

typedef unsigned long long ull;

__device__ float g_xproj[32768u * 1024u];   // 128 MB scratch

__device__ __forceinline__ void fma2(ull& d, ull a, ull b) {
    asm("fma.rn.f32x2 %0, %1, %2, %0;" : "+l"(d) : "l"(a), "l"(b));
}
__device__ __forceinline__ ull splat2(float x) {
    ull r; asm("mov.b64 %0, {%1, %1};" : "=l"(r) : "f"(x)); return r;
}
__device__ __forceinline__ ull pack2(float a, float b) {
    ull r; asm("mov.b64 %0, {%1, %2};" : "=l"(r) : "f"(a), "f"(b)); return r;
}
__device__ __forceinline__ float2 unpack2(ull v) {
    float2 r; asm("mov.b64 {%0, %1}, %2;" : "=f"(r.x), "=f"(r.y) : "l"(v)); return r;
}
__device__ __forceinline__ float rcpf(float x) {
    float r; asm("rcp.approx.f32 %0, %1;" : "=f"(r) : "f"(x)); return r;
}
__device__ __forceinline__ uint32_t smem_u32(const void* p) {
    uint32_t a;
    asm("{ .reg .u64 t; cvta.to.shared.u64 t, %1; cvt.u32.u64 %0, t; }"
        : "=r"(a) : "l"(p));
    return a;
}

// ---------------------------------------------------------------------------
// Phase 1: xproj GEMM (unchanged).
// ---------------------------------------------------------------------------
__global__ __launch_bounds__(256) void xproj_kernel(const float* __restrict__ X,
                                                    const float* __restrict__ Wi,
                                                    const float* __restrict__ Bias) {
    __shared__ __align__(16) float As_t[32 * 68];
    __shared__ __align__(16) float Bs[32 * 64];

    const int tid = threadIdx.x;
    const int m0 = blockIdx.y * 64;
    const int n0 = blockIdx.x * 64;
    const int tm = tid >> 4, tn = tid & 15;

    ull acc[4][2];
#pragma unroll
    for (int i = 0; i < 4; ++i) { acc[i][0] = 0ull; acc[i][1] = 0ull; }

    const float4* X4  = (const float4*)X;
    const float4* Wi4 = (const float4*)Wi;

    for (int kt = 0; kt < 128; kt += 32) {
#pragma unroll
        for (int i = 0; i < 2; ++i) {
            int f = tid + i * 256;
            int row = f >> 3, kk4 = f & 7;
            float4 v = X4[(size_t)(m0 + row) * 32 + (kt >> 2) + kk4];
            As_t[(kk4 * 4 + 0) * 68 + row] = v.x;
            As_t[(kk4 * 4 + 1) * 68 + row] = v.y;
            As_t[(kk4 * 4 + 2) * 68 + row] = v.z;
            As_t[(kk4 * 4 + 3) * 68 + row] = v.w;
        }
#pragma unroll
        for (int i = 0; i < 2; ++i) {
            int f = tid + i * 256;
            int row = f >> 4, c4 = f & 15;
            *(float4*)(Bs + row * 64 + c4 * 4) =
                Wi4[(size_t)(kt + row) * 256 + (n0 >> 2) + c4];
        }
        __syncthreads();
#pragma unroll
        for (int kk = 0; kk < 32; ++kk) {
            float4 a4 = *(const float4*)(As_t + kk * 68 + tm * 4);
            ulonglong2 b2 = *(const ulonglong2*)(Bs + kk * 64 + tn * 4);
            ull s;
            s = splat2(a4.x); fma2(acc[0][0], s, b2.x); fma2(acc[0][1], s, b2.y);
            s = splat2(a4.y); fma2(acc[1][0], s, b2.x); fma2(acc[1][1], s, b2.y);
            s = splat2(a4.z); fma2(acc[2][0], s, b2.x); fma2(acc[2][1], s, b2.y);
            s = splat2(a4.w); fma2(acc[3][0], s, b2.x); fma2(acc[3][1], s, b2.y);
        }
        __syncthreads();
    }

    float4 bias = *(const float4*)(Bias + n0 + tn * 4);
#pragma unroll
    for (int i = 0; i < 4; ++i) {
        float2 p0 = unpack2(acc[i][0]);
        float2 p1 = unpack2(acc[i][1]);
        float4 o = make_float4(p0.x + bias.x, p0.y + bias.y,
                               p1.x + bias.z, p1.y + bias.w);
        *(float4*)(g_xproj + (size_t)(m0 + tm * 4 + i) * 1024 + n0 + tn * 4) = o;
    }
}

// ---------------------------------------------------------------------------
// Phase 2: mbarrier-synced all-in-warp recurrence.
//   hsm[2][2048]: two 8192-byte buffers; used layout per buffer:
//   [batch b][k-seg s] at b*272 + s*68 (skewed, conflict-free LDS.128).
//   h(t) lives in buf[t&1], signaled on mbar[t&1], parity (t>>1)&1.
// ---------------------------------------------------------------------------
__global__ __launch_bounds__(512, 1) __cluster_dims__(8, 1, 1)
void lstm_rec(const float* __restrict__ Wh, float* __restrict__ out) {
    __shared__ __align__(16) float hsm[2][2048];
    __shared__ __align__(8) ull mbars[2];

    const int tid  = threadIdx.x;
    const int lane = tid & 31;
    const int warp = tid >> 5;
    const int cl   = lane & 7;
    const int s    = lane >> 3;          // k-segment == my batch index
    const int ga   = cl & 3;             // gate
    const int jh   = cl >> 2;            // which of the warp's 2 h-dims

    uint32_t rank;
    asm("mov.u32 %0, %%cluster_ctarank;" : "=r"(rank));
    const int r     = (int)rank;
    const int b0    = (blockIdx.x >> 3) * 4;     // first batch of cluster
    const int jjl   = 2 * warp + jh;             // local h-dim 0..31
    const int koff  = r * 32 + jjl;              // global h index
    const int colg  = ga * 256 + koff;           // global gate column
    const int kbase = s * 64;

    // --- Wh slice -> registers (one-time) ---
    ull wreg[32];
#pragma unroll
    for (int i = 0; i < 32; ++i) {
        float wa = __ldg(&Wh[(size_t)(kbase + 2 * i) * 1024 + colg]);
        float wb = __ldg(&Wh[(size_t)(kbase + 2 * i + 1) * 1024 + colg]);
        wreg[i] = pack2(wa, wb);
    }

    // zero both h buffers; init mbarriers (128 arrivals = 16 warps x 8 CTAs)
    for (int i = tid; i < 4096; i += 512) ((float*)hsm)[i] = 0.0f;
    const uint32_t lmb = smem_u32(mbars);
    if (tid == 0) {
        asm volatile("mbarrier.init.shared.b64 [%0], 128;" :: "r"(lmb) : "memory");
        asm volatile("mbarrier.init.shared.b64 [%0], 128;" :: "r"(lmb + 8) : "memory");
    }
    __syncthreads();
    // one-time cluster rendezvous: all inits + zeroing visible before any
    // remote push/arrive can land.
    asm volatile("barrier.cluster.arrive.aligned;" ::: "memory");
    asm volatile("barrier.cluster.wait.aligned;"   ::: "memory");

    // hoisted DSMEM push addresses (mapa results are stable)
    const uint32_t hsm_base = smem_u32(hsm);
    const int      cell_off = (koff >> 6) * 68 + (koff & 63);
    const uint32_t loc = hsm_base + (uint32_t)((s * 272 + cell_off) * 4);
    uint32_t pa1, pa2;
    asm("mapa.shared::cluster.u32 %0, %1, %2;" : "=r"(pa1) : "r"(loc), "r"(ga));
    asm("mapa.shared::cluster.u32 %0, %1, %2;" : "=r"(pa2) : "r"(loc), "r"(ga + 4));

    // gate activation: i,f,o -> sigmoid(x); g -> tanh(x) = 2*sigmoid(2x)-1
    const float am = (ga == 2) ? 2.0f : 1.0f;
    const float om = (ga == 2) ? 2.0f : 1.0f;
    const float ob = (ga == 2) ? -1.0f : 0.0f;

    const unsigned base_src = (unsigned)(lane & 0x1C);   // s*8 + jh*4
    const bool     writer   = (ga == 0);                 // 1 of 4 redundant lanes

    const float* xpp  = g_xproj + (size_t)(b0 + s) * 512 * 1024 + colg;
    float*       outp = out + (size_t)(b0 + s) * 512 * 256 + koff;

    float xp  = __ldg(xpp);    // t = 0
    float cre = 0.0f;

#pragma unroll 1
    for (int t = 0; t < 512; ++t) {
        if (t > 0) {
            // wait for h(t-1): mbar[(t-1)&1], parity ((t-1)>>1)&1
            const int u = t - 1;
            uint32_t mw = lmb + (uint32_t)((u & 1) << 3);
            uint32_t pr = (uint32_t)((u >> 1) & 1);
            asm volatile(
                "{\n\t.reg .pred P;\n"
                "W_%=:\n\t"
                "mbarrier.try_wait.parity.acquire.cluster.shared::cta.b64 P, [%0], %1, 0x989680;\n\t"
                "@P bra.uni D_%=;\n\t"
                "bra.uni W_%=;\n\t"
                "D_%=:\n\t}"
                :: "r"(mw), "r"(pr) : "memory");
        }

        const float* hb = hsm[(t + 1) & 1];              // h(t-1) buffer
        const ulonglong2* h0 = (const ulonglong2*)(hb + 0 * 272 + s * 68);
        const ulonglong2* h1 = (const ulonglong2*)(hb + 1 * 272 + s * 68);
        const ulonglong2* h2 = (const ulonglong2*)(hb + 2 * 272 + s * 68);
        const ulonglong2* h3 = (const ulonglong2*)(hb + 3 * 272 + s * 68);

        ull a0 = 0, a1 = 0, a2 = 0, a3 = 0;
#pragma unroll
        for (int i = 0; i < 16; ++i) {
            ulonglong2 v0 = h0[i];
            ulonglong2 v1 = h1[i];
            ulonglong2 v2 = h2[i];
            ulonglong2 v3 = h3[i];
            fma2(a0, wreg[2 * i], v0.x); fma2(a0, wreg[2 * i + 1], v0.y);
            fma2(a1, wreg[2 * i], v1.x); fma2(a1, wreg[2 * i + 1], v1.y);
            fma2(a2, wreg[2 * i], v2.x); fma2(a2, wreg[2 * i + 1], v2.y);
            fma2(a3, wreg[2 * i], v3.x); fma2(a3, wreg[2 * i + 1], v3.y);
        }

        float2 p;
        float d0, d1, d2, d3;
        p = unpack2(a0); d0 = p.x + p.y;
        p = unpack2(a1); d1 = p.x + p.y;
        p = unpack2(a2); d2 = p.x + p.y;
        p = unpack2(a3); d3 = p.x + p.y;

        d0 += __shfl_xor_sync(0xffffffffu, d0, 8);
        d1 += __shfl_xor_sync(0xffffffffu, d1, 8);
        d2 += __shfl_xor_sync(0xffffffffu, d2, 8);
        d3 += __shfl_xor_sync(0xffffffffu, d3, 8);
        d0 += __shfl_xor_sync(0xffffffffu, d0, 16);
        d1 += __shfl_xor_sync(0xffffffffu, d1, 16);
        d2 += __shfl_xor_sync(0xffffffffu, d2, 16);
        d3 += __shfl_xor_sync(0xffffffffu, d3, 16);

        float ds = (s == 0) ? d0 : (s == 1) ? d1 : (s == 2) ? d2 : d3;
        float gx = xp + ds;
        float u_ = __expf(-am * gx);
        float sg = rcpf(1.0f + u_);
        float e  = fmaf(sg, om, ob);

        float i_ = __shfl_sync(0xffffffffu, e, base_src | 0);
        float f_ = __shfl_sync(0xffffffffu, e, base_src | 1);
        float g_ = __shfl_sync(0xffffffffu, e, base_src | 2);
        float o_ = __shfl_sync(0xffffffffu, e, base_src | 3);

        cre = fmaf(f_, cre, i_ * g_);
        float u2 = __expf(-2.0f * cre);
        float th = (1.0f - u2) * rcpf(1.0f + u2);   // tanh(cre)
        float hn = o_ * th;

        if (t < 511) {
            // push h(t) into buf[t&1] of my 2 dest CTAs, then signal all 8.
            uint32_t boff = (uint32_t)((t & 1) << 13);
            asm volatile("st.shared::cluster.f32 [%0], %1;"
                         :: "r"(pa1 + boff), "f"(hn) : "memory");
            asm volatile("st.shared::cluster.f32 [%0], %1;"
                         :: "r"(pa2 + boff), "f"(hn) : "memory");
            __syncwarp();
            if (lane == 0) {
                uint32_t lm = lmb + (uint32_t)((t & 1) << 3);
#pragma unroll
                for (int d = 0; d < 8; ++d) {
                    uint32_t ra;
                    asm("mapa.shared::cluster.u32 %0, %1, %2;"
                        : "=r"(ra) : "r"(lm), "r"(d));
                    asm volatile(
                        "mbarrier.arrive.release.cluster.shared::cluster.b64 _, [%0];"
                        :: "r"(ra) : "memory");
                }
            }
        }

        // off-critical-path: output store + next-step xproj prefetch
        if (writer) outp[(size_t)t * 256] = hn;
        if (t < 511) {
            xp = __ldg(xpp + (size_t)(t + 1) * 1024);
        } else if (writer) {
            out[8388608u + (size_t)(b0 + s) * 256 + koff]          = hn;   // ht
            out[8388608u + 16384u + (size_t)(b0 + s) * 256 + koff] = cre;  // ct
        }
    }
}

// ---------------------------------------------------------------------------
extern "C" void kernel_launch(void* const* d_in, const int* in_sizes, int n_in,
                              void* d_out, int out_size) {
    const float* x  = nullptr;   // 64*512*128 = 4194304
    const float* Wi = nullptr;   // 128*1024   = 131072
    const float* Wh = nullptr;   // 256*1024   = 262144
    const float* Bb = nullptr;   // 1024
    for (int i = 0; i < n_in; ++i) {
        switch (in_sizes[i]) {
            case 4194304: x  = (const float*)d_in[i]; break;
            case 131072:  Wi = (const float*)d_in[i]; break;
            case 262144:  Wh = (const float*)d_in[i]; break;
            case 1024:    Bb = (const float*)d_in[i]; break;
            default: break;
        }
    }
    float* out = (float*)d_out;
    (void)out_size;

    xproj_kernel<<<dim3(16, 512), 256>>>(x, Wi, Bb);
    lstm_rec<<<128, 512>>>(Wh, out);
}

// round 6
// speedup vs baseline: 2.0338x; 2.0338x over previous
#include <cuda_runtime.h>
#include <cstdint>

// ---------------------------------------------------------------------------
// ChaoticLSTM: bs=64, seq=512, in=128, H=256, 4H=1024, T=512
//   Phase 1: xproj[32768][1024] = X[32768][128] @ Wi[128][1024] + B
//   Phase 2: register-stationary-Wh recurrence, 16 clusters x 8 CTAs x 512 thr.
//     R6: per-step all-to-all = 8 DSMEM BULK copies (512B each) with
//     mbarrier::complete_tx::bytes. 8 tx-completions/step/CTA instead of
//     128 arrivals (R5) or a full cluster thread-rendezvous (R3/R4).
// ---------------------------------------------------------------------------

typedef unsigned long long ull;

__device__ float g_xproj[32768u * 1024u];   // 128 MB scratch

__device__ __forceinline__ void fma2(ull& d, ull a, ull b) {
    asm("fma.rn.f32x2 %0, %1, %2, %0;" : "+l"(d) : "l"(a), "l"(b));
}
__device__ __forceinline__ ull splat2(float x) {
    ull r; asm("mov.b64 %0, {%1, %1};" : "=l"(r) : "f"(x)); return r;
}
__device__ __forceinline__ ull pack2(float a, float b) {
    ull r; asm("mov.b64 %0, {%1, %2};" : "=l"(r) : "f"(a), "f"(b)); return r;
}
__device__ __forceinline__ float2 unpack2(ull v) {
    float2 r; asm("mov.b64 {%0, %1}, %2;" : "=f"(r.x), "=f"(r.y) : "l"(v)); return r;
}
__device__ __forceinline__ float rcpf(float x) {
    float r; asm("rcp.approx.f32 %0, %1;" : "=f"(r) : "f"(x)); return r;
}
__device__ __forceinline__ uint32_t smem_u32(const void* p) {
    uint32_t a;
    asm("{ .reg .u64 t; cvta.to.shared.u64 t, %1; cvt.u32.u64 %0, t; }"
        : "=r"(a) : "l"(p));
    return a;
}

// ---------------------------------------------------------------------------
// Phase 1: xproj GEMM (unchanged).
// ---------------------------------------------------------------------------
__global__ __launch_bounds__(256) void xproj_kernel(const float* __restrict__ X,
                                                    const float* __restrict__ Wi,
                                                    const float* __restrict__ Bias) {
    __shared__ __align__(16) float As_t[32 * 68];
    __shared__ __align__(16) float Bs[32 * 64];

    const int tid = threadIdx.x;
    const int m0 = blockIdx.y * 64;
    const int n0 = blockIdx.x * 64;
    const int tm = tid >> 4, tn = tid & 15;

    ull acc[4][2];
#pragma unroll
    for (int i = 0; i < 4; ++i) { acc[i][0] = 0ull; acc[i][1] = 0ull; }

    const float4* X4  = (const float4*)X;
    const float4* Wi4 = (const float4*)Wi;

    for (int kt = 0; kt < 128; kt += 32) {
#pragma unroll
        for (int i = 0; i < 2; ++i) {
            int f = tid + i * 256;
            int row = f >> 3, kk4 = f & 7;
            float4 v = X4[(size_t)(m0 + row) * 32 + (kt >> 2) + kk4];
            As_t[(kk4 * 4 + 0) * 68 + row] = v.x;
            As_t[(kk4 * 4 + 1) * 68 + row] = v.y;
            As_t[(kk4 * 4 + 2) * 68 + row] = v.z;
            As_t[(kk4 * 4 + 3) * 68 + row] = v.w;
        }
#pragma unroll
        for (int i = 0; i < 2; ++i) {
            int f = tid + i * 256;
            int row = f >> 4, c4 = f & 15;
            *(float4*)(Bs + row * 64 + c4 * 4) =
                Wi4[(size_t)(kt + row) * 256 + (n0 >> 2) + c4];
        }
        __syncthreads();
#pragma unroll
        for (int kk = 0; kk < 32; ++kk) {
            float4 a4 = *(const float4*)(As_t + kk * 68 + tm * 4);
            ulonglong2 b2 = *(const ulonglong2*)(Bs + kk * 64 + tn * 4);
            ull s;
            s = splat2(a4.x); fma2(acc[0][0], s, b2.x); fma2(acc[0][1], s, b2.y);
            s = splat2(a4.y); fma2(acc[1][0], s, b2.x); fma2(acc[1][1], s, b2.y);
            s = splat2(a4.z); fma2(acc[2][0], s, b2.x); fma2(acc[2][1], s, b2.y);
            s = splat2(a4.w); fma2(acc[3][0], s, b2.x); fma2(acc[3][1], s, b2.y);
        }
        __syncthreads();
    }

    float4 bias = *(const float4*)(Bias + n0 + tn * 4);
#pragma unroll
    for (int i = 0; i < 4; ++i) {
        float2 p0 = unpack2(acc[i][0]);
        float2 p1 = unpack2(acc[i][1]);
        float4 o = make_float4(p0.x + bias.x, p0.y + bias.y,
                               p1.x + bias.z, p1.y + bias.w);
        *(float4*)(g_xproj + (size_t)(m0 + tm * 4 + i) * 1024 + n0 + tn * 4) = o;
    }
}

// ---------------------------------------------------------------------------
// Phase 2: bulk-copy all-to-all recurrence.
//
// h buffer (per CTA): hbuf[2][8 ranks x 132 floats]. Rank block = 512B of
// payload, layout [j4 0..7][batch 0..3][4 floats]; rank stride padded to
// 528B so a warp's 4 simultaneous k-segments hit distinct bank groups.
// h index of (r, j4, f) = r*32 + j4*4 + f; k = 2*i_w identity keeps the
// wreg load formula identical to R4.
// Staging (per CTA): stage[2][128] floats, same [j4][b][f] layout.
// mbar[2]: init count 1; per step tid0 arms expect_tx(4096); 8 incoming
// 512B bulks complete the phase. Parity of step u on mbar[u&1] = (u>>1)&1.
// ---------------------------------------------------------------------------
#define RSTRIDE 132                     // floats per rank block (528 B)
#define HBUFSZ  (8 * RSTRIDE)           // 1056 floats per buffer

__global__ __launch_bounds__(512, 1) __cluster_dims__(8, 1, 1)
void lstm_rec(const float* __restrict__ Wh, float* __restrict__ out) {
    __shared__ __align__(16) float hbuf[2][HBUFSZ];
    __shared__ __align__(16) float stage[2][128];
    __shared__ __align__(8)  ull   mbars[2];

    const int tid  = threadIdx.x;
    const int lane = tid & 31;
    const int warp = tid >> 5;
    const int cl   = lane & 7;
    const int s    = lane >> 3;          // k-segment == my batch index
    const int ga   = cl & 3;             // gate
    const int jh   = cl >> 2;            // which of the warp's 2 h-dims

    uint32_t rank;
    asm("mov.u32 %0, %%cluster_ctarank;" : "=r"(rank));
    const int r     = (int)rank;
    const int b0    = (blockIdx.x >> 3) * 4;     // first batch of cluster
    const int jjl   = 2 * warp + jh;             // local h-dim 0..31
    const int koff  = r * 32 + jjl;              // global h index
    const int colg  = ga * 256 + koff;           // global gate column
    const int kbase = s * 64;

    // --- Wh slice -> registers (one-time). wreg[i] covers k = kbase+2i. ---
    ull wreg[32];
#pragma unroll
    for (int i = 0; i < 32; ++i) {
        float wa = __ldg(&Wh[(size_t)(kbase + 2 * i) * 1024 + colg]);
        float wb = __ldg(&Wh[(size_t)(kbase + 2 * i + 1) * 1024 + colg]);
        wreg[i] = pack2(wa, wb);
    }

    // zero h buffers (h(-1)=0); init mbarriers (count 1, tx-driven)
    for (int i = tid; i < 2 * HBUFSZ; i += 512) ((float*)hbuf)[i] = 0.0f;
    const uint32_t lmb = smem_u32(mbars);
    if (tid == 0) {
        asm volatile("mbarrier.init.shared.b64 [%0], 1;" :: "r"(lmb) : "memory");
        asm volatile("mbarrier.init.shared.b64 [%0], 1;" :: "r"(lmb + 8) : "memory");
    }
    __syncthreads();
    // one-time cluster rendezvous: zeroing + mbar init visible cluster-wide
    asm volatile("barrier.cluster.arrive.aligned;" ::: "memory");
    asm volatile("barrier.cluster.wait.aligned;"   ::: "memory");

    // hoisted remote base addresses for sender lanes (tid 0..7 -> dest CTA)
    const uint32_t hbase  = smem_u32(hbuf);
    const uint32_t sbase  = smem_u32(stage);
    uint32_t rem_h = 0, rem_m = 0;
    if (tid < 8) {
        asm("mapa.shared::cluster.u32 %0, %1, %2;" : "=r"(rem_h) : "r"(hbase), "r"(tid));
        asm("mapa.shared::cluster.u32 %0, %1, %2;" : "=r"(rem_m) : "r"(lmb),   "r"(tid));
    }

    // gate activation: i,f,o -> sigmoid(x); g -> tanh(x) = 2*sigmoid(2x)-1
    const float am = (ga == 2) ? 2.0f : 1.0f;
    const float om = (ga == 2) ? 2.0f : 1.0f;
    const float ob = (ga == 2) ? -1.0f : 0.0f;

    const unsigned base_src = (unsigned)(lane & 0x1C);   // s*8 + jh*4
    const bool     writer   = (ga == 0);
    // writer's slot in staging: [j4][b][f] = (jjl>>2)*16 + s*4 + (jjl&3)
    const int wslot = (jjl >> 2) * 16 + s * 4 + (jjl & 3);

    const float* xpp  = g_xproj + (size_t)(b0 + s) * 512 * 1024 + colg;
    float*       outp = out + (size_t)(b0 + s) * 512 * 256 + koff;

    float xp  = __ldg(xpp);    // t = 0
    float cre = 0.0f;

#pragma unroll 1
    for (int t = 0; t < 512; ++t) {
        if (t > 0) {
            // wait for h(t-1): mbar[(t-1)&1], parity ((t-1)>>1)&1
            const int u = t - 1;
            uint32_t mw = lmb + (uint32_t)((u & 1) << 3);
            uint32_t pr = (uint32_t)((u >> 1) & 1);
            asm volatile(
                "{\n\t.reg .pred P;\n"
                "W_%=:\n\t"
                "mbarrier.try_wait.parity.acquire.cta.shared::cta.b64 P, [%0], %1, 0x989680;\n\t"
                "@P bra.uni D_%=;\n\t"
                "bra.uni W_%=;\n\t"
                "D_%=:\n\t}"
                :: "r"(mw), "r"(pr) : "memory");
        }
        // arm mbar[t&1] for incoming h(t) (phase known flipped: tid0 waited
        // on this mbar at step t-1)
        if (tid == 0 && t < 511) {
            uint32_t ma = lmb + (uint32_t)((t & 1) << 3);
            asm volatile("mbarrier.arrive.expect_tx.shared.b64 _, [%0], %1;"
                         :: "r"(ma), "r"(4096u) : "memory");
        }

        // ---- dot: my 64-k segment (ranks 2s, 2s+1), 4 batches ----
        const float* hb = hbuf[(t + 1) & 1];   // h(t-1)
        ull a0 = 0, a1 = 0, a2 = 0, a3 = 0;
#pragma unroll
        for (int rr = 0; rr < 2; ++rr) {
            const float* rbase = hb + (2 * s + rr) * RSTRIDE;
#pragma unroll
            for (int j4 = 0; j4 < 8; ++j4) {
                const float* q = rbase + j4 * 16;
                ulonglong2 v0 = *(const ulonglong2*)(q + 0);
                ulonglong2 v1 = *(const ulonglong2*)(q + 4);
                ulonglong2 v2 = *(const ulonglong2*)(q + 8);
                ulonglong2 v3 = *(const ulonglong2*)(q + 12);
                int iw = rr * 16 + j4 * 2;
                fma2(a0, wreg[iw], v0.x); fma2(a0, wreg[iw + 1], v0.y);
                fma2(a1, wreg[iw], v1.x); fma2(a1, wreg[iw + 1], v1.y);
                fma2(a2, wreg[iw], v2.x); fma2(a2, wreg[iw + 1], v2.y);
                fma2(a3, wreg[iw], v3.x); fma2(a3, wreg[iw + 1], v3.y);
            }
        }

        float2 p;
        float d0, d1, d2, d3;
        p = unpack2(a0); d0 = p.x + p.y;
        p = unpack2(a1); d1 = p.x + p.y;
        p = unpack2(a2); d2 = p.x + p.y;
        p = unpack2(a3); d3 = p.x + p.y;

        d0 += __shfl_xor_sync(0xffffffffu, d0, 8);
        d1 += __shfl_xor_sync(0xffffffffu, d1, 8);
        d2 += __shfl_xor_sync(0xffffffffu, d2, 8);
        d3 += __shfl_xor_sync(0xffffffffu, d3, 8);
        d0 += __shfl_xor_sync(0xffffffffu, d0, 16);
        d1 += __shfl_xor_sync(0xffffffffu, d1, 16);
        d2 += __shfl_xor_sync(0xffffffffu, d2, 16);
        d3 += __shfl_xor_sync(0xffffffffu, d3, 16);

        float ds = (s == 0) ? d0 : (s == 1) ? d1 : (s == 2) ? d2 : d3;
        float gx = xp + ds;
        float u_ = __expf(-am * gx);
        float sg = rcpf(1.0f + u_);
        float e  = fmaf(sg, om, ob);

        float i_ = __shfl_sync(0xffffffffu, e, base_src | 0);
        float f_ = __shfl_sync(0xffffffffu, e, base_src | 1);
        float g_ = __shfl_sync(0xffffffffu, e, base_src | 2);
        float o_ = __shfl_sync(0xffffffffu, e, base_src | 3);

        cre = fmaf(f_, cre, i_ * g_);
        float u2 = __expf(-2.0f * cre);
        float th = (1.0f - u2) * rcpf(1.0f + u2);   // tanh(cre)
        float hn = o_ * th;

        if (writer) stage[t & 1][wslot] = hn;
        __syncthreads();   // staging complete (and all reads of hb retired)

        if (t < 511 && tid < 8) {
            // send my 512B contribution to dest CTA = tid
            asm volatile("fence.proxy.async.shared::cta;" ::: "memory");
            uint32_t src = sbase + (uint32_t)((t & 1) * 512);
            uint32_t dst = rem_h + (uint32_t)((t & 1) * (HBUFSZ * 4) + r * (RSTRIDE * 4));
            uint32_t mba = rem_m + (uint32_t)((t & 1) << 3);
            asm volatile(
                "cp.async.bulk.shared::cluster.shared::cta.mbarrier::complete_tx::bytes "
                "[%0], [%1], %2, [%3];"
                :: "r"(dst), "r"(src), "r"(512u), "r"(mba) : "memory");
        }

        // off-critical-path: output store + next-step xproj prefetch
        if (writer) outp[(size_t)t * 256] = hn;
        if (t < 511) {
            xp = __ldg(xpp + (size_t)(t + 1) * 1024);
        } else if (writer) {
            out[8388608u + (size_t)(b0 + s) * 256 + koff]          = hn;   // ht
            out[8388608u + 16384u + (size_t)(b0 + s) * 256 + koff] = cre;  // ct
        }
    }
}

// ---------------------------------------------------------------------------
extern "C" void kernel_launch(void* const* d_in, const int* in_sizes, int n_in,
                              void* d_out, int out_size) {
    const float* x  = nullptr;   // 64*512*128 = 4194304
    const float* Wi = nullptr;   // 128*1024   = 131072
    const float* Wh = nullptr;   // 256*1024   = 262144
    const float* Bb = nullptr;   // 1024
    for (int i = 0; i < n_in; ++i) {
        switch (in_sizes[i]) {
            case 4194304: x  = (const float*)d_in[i]; break;
            case 131072:  Wi = (const float*)d_in[i]; break;
            case 262144:  Wh = (const float*)d_in[i]; break;
            case 1024:    Bb = (const float*)d_in[i]; break;
            default: break;
        }
    }
    float* out = (float*)d_out;
    (void)out_size;

    xproj_kernel<<<dim3(16, 512), 256>>>(x, Wi, Bb);
    lstm_rec<<<128, 512>>>(Wh, out);
}

// round 7
// speedup vs baseline: 2.4878x; 1.2232x over previous
#include <cuda_runtime.h>
#include <cstdint>

// ---------------------------------------------------------------------------
// ChaoticLSTM: bs=64, seq=512, in=128, H=256, 4H=1024, T=512
//   Phase 1: xproj[32768][1024] = X[32768][128] @ Wi[128][1024] + B
//   Phase 2: recurrence, 16 clusters x 8 CTAs x 256 thr.
//     R7: 2 gate-columns per thread (wreg = 64 f32x2), 8 warps/CTA.
//     Sync = R6's 8x512B DSMEM bulk + tx-mbarrier, with bar.arrive/bar.sync
//     producer split and 2-step-deep xproj prefetch.
// ---------------------------------------------------------------------------

typedef unsigned long long ull;

__device__ float g_xproj[32768u * 1024u];   // 128 MB scratch

__device__ __forceinline__ void fma2(ull& d, ull a, ull b) {
    asm("fma.rn.f32x2 %0, %1, %2, %0;" : "+l"(d) : "l"(a), "l"(b));
}
__device__ __forceinline__ ull splat2(float x) {
    ull r; asm("mov.b64 %0, {%1, %1};" : "=l"(r) : "f"(x)); return r;
}
__device__ __forceinline__ ull pack2(float a, float b) {
    ull r; asm("mov.b64 %0, {%1, %2};" : "=l"(r) : "f"(a), "f"(b)); return r;
}
__device__ __forceinline__ float2 unpack2(ull v) {
    float2 r; asm("mov.b64 {%0, %1}, %2;" : "=f"(r.x), "=f"(r.y) : "l"(v)); return r;
}
__device__ __forceinline__ float rcpf(float x) {
    float r; asm("rcp.approx.f32 %0, %1;" : "=f"(r) : "f"(x)); return r;
}
__device__ __forceinline__ uint32_t smem_u32(const void* p) {
    uint32_t a;
    asm("{ .reg .u64 t; cvta.to.shared.u64 t, %1; cvt.u32.u64 %0, t; }"
        : "=r"(a) : "l"(p));
    return a;
}

// ---------------------------------------------------------------------------
// Phase 1: xproj GEMM (unchanged).
// ---------------------------------------------------------------------------
__global__ __launch_bounds__(256) void xproj_kernel(const float* __restrict__ X,
                                                    const float* __restrict__ Wi,
                                                    const float* __restrict__ Bias) {
    __shared__ __align__(16) float As_t[32 * 68];
    __shared__ __align__(16) float Bs[32 * 64];

    const int tid = threadIdx.x;
    const int m0 = blockIdx.y * 64;
    const int n0 = blockIdx.x * 64;
    const int tm = tid >> 4, tn = tid & 15;

    ull acc[4][2];
#pragma unroll
    for (int i = 0; i < 4; ++i) { acc[i][0] = 0ull; acc[i][1] = 0ull; }

    const float4* X4  = (const float4*)X;
    const float4* Wi4 = (const float4*)Wi;

    for (int kt = 0; kt < 128; kt += 32) {
#pragma unroll
        for (int i = 0; i < 2; ++i) {
            int f = tid + i * 256;
            int row = f >> 3, kk4 = f & 7;
            float4 v = X4[(size_t)(m0 + row) * 32 + (kt >> 2) + kk4];
            As_t[(kk4 * 4 + 0) * 68 + row] = v.x;
            As_t[(kk4 * 4 + 1) * 68 + row] = v.y;
            As_t[(kk4 * 4 + 2) * 68 + row] = v.z;
            As_t[(kk4 * 4 + 3) * 68 + row] = v.w;
        }
#pragma unroll
        for (int i = 0; i < 2; ++i) {
            int f = tid + i * 256;
            int row = f >> 4, c4 = f & 15;
            *(float4*)(Bs + row * 64 + c4 * 4) =
                Wi4[(size_t)(kt + row) * 256 + (n0 >> 2) + c4];
        }
        __syncthreads();
#pragma unroll
        for (int kk = 0; kk < 32; ++kk) {
            float4 a4 = *(const float4*)(As_t + kk * 68 + tm * 4);
            ulonglong2 b2 = *(const ulonglong2*)(Bs + kk * 64 + tn * 4);
            ull s;
            s = splat2(a4.x); fma2(acc[0][0], s, b2.x); fma2(acc[0][1], s, b2.y);
            s = splat2(a4.y); fma2(acc[1][0], s, b2.x); fma2(acc[1][1], s, b2.y);
            s = splat2(a4.z); fma2(acc[2][0], s, b2.x); fma2(acc[2][1], s, b2.y);
            s = splat2(a4.w); fma2(acc[3][0], s, b2.x); fma2(acc[3][1], s, b2.y);
        }
        __syncthreads();
    }

    float4 bias = *(const float4*)(Bias + n0 + tn * 4);
#pragma unroll
    for (int i = 0; i < 4; ++i) {
        float2 p0 = unpack2(acc[i][0]);
        float2 p1 = unpack2(acc[i][1]);
        float4 o = make_float4(p0.x + bias.x, p0.y + bias.y,
                               p1.x + bias.z, p1.y + bias.w);
        *(float4*)(g_xproj + (size_t)(m0 + tm * 4 + i) * 1024 + n0 + tn * 4) = o;
    }
}

// ---------------------------------------------------------------------------
// Phase 2: 256-thread, 2-columns-per-thread recurrence.
//
// Thread map: warp w (0..7); lane: s = lane>>3 (k-segment == batch),
//   cl = lane&7, m = cl>>1 (dim-within-warp), q = cl&1 (gate-pair).
//   Local h-dim j = w*4+m (0..31); koff = r*32+j.
//   Columns: gates {2q, 2q+1} of dim j -> colg_c = (2q+c)*256 + koff.
//   Gate 2 (tanh) lands on q=1,c=0; all others sigmoid.
// h buffer layout (per CTA): hbuf[2][8 ranks x 132f]; rank block =
//   [j4 0..7][batch 0..3][4f] (512B payload, 528B stride: the 4 s-groups of a
//   warp land 32B apart mod 128B -> conflict-free broadcast LDS.128).
// Sync: mbar[2] (count 1), tid0 arms expect_tx(4096) per step; 8x512B
//   cp.async.bulk sends (warp 0, lanes 0..7) after bar 1 producer split.
// ---------------------------------------------------------------------------
#define RSTRIDE 132
#define HBUFSZ  (8 * RSTRIDE)

__global__ __launch_bounds__(256, 1) __cluster_dims__(8, 1, 1)
void lstm_rec(const float* __restrict__ Wh, float* __restrict__ out) {
    __shared__ __align__(16) float hbuf[2][HBUFSZ];
    __shared__ __align__(16) float stage[2][128];
    __shared__ __align__(8)  ull   mbars[2];

    const int tid  = threadIdx.x;
    const int lane = tid & 31;
    const int w    = tid >> 5;           // 0..7
    const int s    = lane >> 3;          // k-segment == my batch index
    const int cl   = lane & 7;
    const int m    = cl >> 1;            // 0..3
    const int q    = cl & 1;             // gate-pair selector

    uint32_t rank;
    asm("mov.u32 %0, %%cluster_ctarank;" : "=r"(rank));
    const int r     = (int)rank;
    const int b0    = (blockIdx.x >> 3) * 4;
    const int j     = w * 4 + m;                 // local h-dim 0..31
    const int koff  = r * 32 + j;
    const int colg0 = (2 * q) * 256 + koff;      // gates {2q, 2q+1}
    const int colg1 = (2 * q + 1) * 256 + koff;
    const int kbase = s * 64;

    // --- Wh slices -> registers (one-time): 64 f32x2 per thread ---
    ull wreg0[32], wreg1[32];
#pragma unroll
    for (int i = 0; i < 32; ++i) {
        const float* p0 = Wh + (size_t)(kbase + 2 * i) * 1024;
        const float* p1 = Wh + (size_t)(kbase + 2 * i + 1) * 1024;
        wreg0[i] = pack2(__ldg(p0 + colg0), __ldg(p1 + colg0));
        wreg1[i] = pack2(__ldg(p0 + colg1), __ldg(p1 + colg1));
    }

    // zero h buffers; init mbarriers (count 1, tx-driven)
    for (int i = tid; i < 2 * HBUFSZ; i += 256) ((float*)hbuf)[i] = 0.0f;
    const uint32_t lmb = smem_u32(mbars);
    if (tid == 0) {
        asm volatile("mbarrier.init.shared.b64 [%0], 1;" :: "r"(lmb) : "memory");
        asm volatile("mbarrier.init.shared.b64 [%0], 1;" :: "r"(lmb + 8) : "memory");
    }
    __syncthreads();
    asm volatile("barrier.cluster.arrive.aligned;" ::: "memory");
    asm volatile("barrier.cluster.wait.aligned;"   ::: "memory");

    // hoisted remote addresses for sender lanes (tid 0..7 -> dest CTA = tid)
    const uint32_t hbase = smem_u32(hbuf);
    const uint32_t sbase = smem_u32(stage);
    uint32_t rem_h = 0, rem_m = 0;
    if (tid < 8) {
        asm("mapa.shared::cluster.u32 %0, %1, %2;" : "=r"(rem_h) : "r"(hbase), "r"(tid));
        asm("mapa.shared::cluster.u32 %0, %1, %2;" : "=r"(rem_m) : "r"(lmb),   "r"(tid));
    }

    // activation params: c0 = gate 2q (tanh iff q==1), c1 = gate 2q+1 (sigmoid)
    const float am0 = q ? 2.0f : 1.0f;
    const float om0 = q ? 2.0f : 1.0f;
    const float ob0 = q ? -1.0f : 0.0f;

    const bool cellw = (q == 0);
    const int  wslot = w * 16 + s * 4 + m;       // stage slot [j4=w][b=s][f=m]

    const float* xpp0 = g_xproj + (size_t)(b0 + s) * 512 * 1024 + colg0;
    const float* xpp1 = g_xproj + (size_t)(b0 + s) * 512 * 1024 + colg1;
    float*       outp = out + (size_t)(b0 + s) * 512 * 256 + koff;

    // 2-step-deep xproj prefetch
    float xc0 = __ldg(xpp0), xc1 = __ldg(xpp1);
    float xn0 = __ldg(xpp0 + 1024), xn1 = __ldg(xpp1 + 1024);

    float cre = 0.0f, hlast = 0.0f;

#pragma unroll 1
    for (int t = 0; t < 512; ++t) {
        if (t > 0) {
            const int u = t - 1;
            uint32_t mw = lmb + (uint32_t)((u & 1) << 3);
            uint32_t pr = (uint32_t)((u >> 1) & 1);
            asm volatile(
                "{\n\t.reg .pred P;\n"
                "W_%=:\n\t"
                "mbarrier.try_wait.parity.acquire.cta.shared::cta.b64 P, [%0], %1, 0x989680;\n\t"
                "@P bra.uni D_%=;\n\t"
                "bra.uni W_%=;\n\t"
                "D_%=:\n\t}"
                :: "r"(mw), "r"(pr) : "memory");
        }
        if (tid == 0 && t < 511) {
            uint32_t ma = lmb + (uint32_t)((t & 1) << 3);
            asm volatile("mbarrier.arrive.expect_tx.shared.b64 _, [%0], %1;"
                         :: "r"(ma), "r"(4096u) : "memory");
        }

        // ---- dot: ranks 2s,2s+1 (64 k) x 4 batches x 2 columns ----
        const float* hb = hbuf[(t + 1) & 1];
        ull A00 = 0, A01 = 0, A02 = 0, A03 = 0;
        ull A10 = 0, A11 = 0, A12 = 0, A13 = 0;
#pragma unroll
        for (int rr = 0; rr < 2; ++rr) {
            const float* rbase = hb + (2 * s + rr) * RSTRIDE;
#pragma unroll
            for (int j4 = 0; j4 < 8; ++j4) {
                const float* qp = rbase + j4 * 16;
                ulonglong2 v0 = *(const ulonglong2*)(qp + 0);
                ulonglong2 v1 = *(const ulonglong2*)(qp + 4);
                ulonglong2 v2 = *(const ulonglong2*)(qp + 8);
                ulonglong2 v3 = *(const ulonglong2*)(qp + 12);
                const int iw = rr * 16 + j4 * 2;
                fma2(A00, wreg0[iw], v0.x); fma2(A00, wreg0[iw + 1], v0.y);
                fma2(A01, wreg0[iw], v1.x); fma2(A01, wreg0[iw + 1], v1.y);
                fma2(A02, wreg0[iw], v2.x); fma2(A02, wreg0[iw + 1], v2.y);
                fma2(A03, wreg0[iw], v3.x); fma2(A03, wreg0[iw + 1], v3.y);
                fma2(A10, wreg1[iw], v0.x); fma2(A10, wreg1[iw + 1], v0.y);
                fma2(A11, wreg1[iw], v1.x); fma2(A11, wreg1[iw + 1], v1.y);
                fma2(A12, wreg1[iw], v2.x); fma2(A12, wreg1[iw + 1], v2.y);
                fma2(A13, wreg1[iw], v3.x); fma2(A13, wreg1[iw + 1], v3.y);
            }
        }

        float2 p;
        float d00, d01, d02, d03, d10, d11, d12, d13;
        p = unpack2(A00); d00 = p.x + p.y;
        p = unpack2(A01); d01 = p.x + p.y;
        p = unpack2(A02); d02 = p.x + p.y;
        p = unpack2(A03); d03 = p.x + p.y;
        p = unpack2(A10); d10 = p.x + p.y;
        p = unpack2(A11); d11 = p.x + p.y;
        p = unpack2(A12); d12 = p.x + p.y;
        p = unpack2(A13); d13 = p.x + p.y;

        d00 += __shfl_xor_sync(0xffffffffu, d00, 8);
        d01 += __shfl_xor_sync(0xffffffffu, d01, 8);
        d02 += __shfl_xor_sync(0xffffffffu, d02, 8);
        d03 += __shfl_xor_sync(0xffffffffu, d03, 8);
        d10 += __shfl_xor_sync(0xffffffffu, d10, 8);
        d11 += __shfl_xor_sync(0xffffffffu, d11, 8);
        d12 += __shfl_xor_sync(0xffffffffu, d12, 8);
        d13 += __shfl_xor_sync(0xffffffffu, d13, 8);
        d00 += __shfl_xor_sync(0xffffffffu, d00, 16);
        d01 += __shfl_xor_sync(0xffffffffu, d01, 16);
        d02 += __shfl_xor_sync(0xffffffffu, d02, 16);
        d03 += __shfl_xor_sync(0xffffffffu, d03, 16);
        d10 += __shfl_xor_sync(0xffffffffu, d10, 16);
        d11 += __shfl_xor_sync(0xffffffffu, d11, 16);
        d12 += __shfl_xor_sync(0xffffffffu, d12, 16);
        d13 += __shfl_xor_sync(0xffffffffu, d13, 16);

        // my batch's two gate pre-activations
        float ds0 = (s == 0) ? d00 : (s == 1) ? d01 : (s == 2) ? d02 : d03;
        float ds1 = (s == 0) ? d10 : (s == 1) ? d11 : (s == 2) ? d12 : d13;
        float gx0 = xc0 + ds0;
        float gx1 = xc1 + ds1;

        float u0 = __expf(-am0 * gx0);
        float e0 = fmaf(rcpf(1.0f + u0), om0, ob0);   // gate 2q
        float u1 = __expf(-gx1);
        float e1 = rcpf(1.0f + u1);                   // gate 2q+1 (sigmoid)

        // exchange gate pairs between q=0 and q=1 lanes
        float gg = __shfl_xor_sync(0xffffffffu, e0, 1);  // on q=0: g (tanh)
        float oo = __shfl_xor_sync(0xffffffffu, e1, 1);  // on q=0: o

        float hn = 0.0f;
        if (cellw) {                 // q=0: i=e0, f=e1
            cre = fmaf(e1, cre, e0 * gg);
            float u2 = __expf(-2.0f * cre);
            float th = (1.0f - u2) * rcpf(1.0f + u2);
            hn = oo * th;
            hlast = hn;
            stage[t & 1][wslot] = hn;
        }

        // producer split: warp 0 rendezvous, others just arrive
        if (w == 0) asm volatile("bar.sync 1, 256;" ::: "memory");
        else        asm volatile("bar.arrive 1, 256;" ::: "memory");

        if (t < 511 && tid < 8) {
            asm volatile("fence.proxy.async.shared::cta;" ::: "memory");
            uint32_t src = sbase + (uint32_t)((t & 1) * 512);
            uint32_t dst = rem_h + (uint32_t)((t & 1) * (HBUFSZ * 4) + r * (RSTRIDE * 4));
            uint32_t mba = rem_m + (uint32_t)((t & 1) << 3);
            asm volatile(
                "cp.async.bulk.shared::cluster.shared::cta.mbarrier::complete_tx::bytes "
                "[%0], [%1], %2, [%3];"
                :: "r"(dst), "r"(src), "r"(512u), "r"(mba) : "memory");
        }

        // off-critical-path: output store + rotate 2-deep xproj prefetch
        if (cellw) outp[(size_t)t * 256] = hn;
        xc0 = xn0; xc1 = xn1;
        if (t < 510) {
            xn0 = __ldg(xpp0 + (size_t)(t + 2) * 1024);
            xn1 = __ldg(xpp1 + (size_t)(t + 2) * 1024);
        }
    }

    if (cellw) {
        out[8388608u + (size_t)(b0 + s) * 256 + koff]          = hlast; // ht
        out[8388608u + 16384u + (size_t)(b0 + s) * 256 + koff] = cre;   // ct
    }
}

// ---------------------------------------------------------------------------
extern "C" void kernel_launch(void* const* d_in, const int* in_sizes, int n_in,
                              void* d_out, int out_size) {
    const float* x  = nullptr;   // 64*512*128 = 4194304
    const float* Wi = nullptr;   // 128*1024   = 131072
    const float* Wh = nullptr;   // 256*1024   = 262144
    const float* Bb = nullptr;   // 1024
    for (int i = 0; i < n_in; ++i) {
        switch (in_sizes[i]) {
            case 4194304: x  = (const float*)d_in[i]; break;
            case 131072:  Wi = (const float*)d_in[i]; break;
            case 262144:  Wh = (const float*)d_in[i]; break;
            case 1024:    Bb = (const float*)d_in[i]; break;
            default: break;
        }
    }
    float* out = (float*)d_out;
    (void)out_size;

    xproj_kernel<<<dim3(16, 512), 256>>>(x, Wi, Bb);
    lstm_rec<<<128, 256>>>(Wh, out);
}